// round 12
// baseline (speedup 1.0000x reference)
#include <cuda_runtime.h>
#include <cuda_bf16.h>
#include <math.h>
#include <stdint.h>

#define B_TOK 8192
#define D_DIM 1024
#define DFF   1024
#define E_NUM 32
#define NFLAT (B_TOK*2)
#define NPAD  (NFLAT+128)
#define SEGS  64            // NFLAT / 256

// ---------------- scratch (static device globals; no allocation) ----------------
__device__ int   g_top2[NFLAT];
__device__ int   g_offsets[E_NUM+1];
__device__ int   g_disp[NFLAT];
__device__ int   g_segcnt[E_NUM*SEGS];
__device__ int   g_segbase[E_NUM*SEGS];
__device__ __align__(16) __nv_bfloat16 g_Xh[(size_t)NPAD*D_DIM];
__device__ __align__(16) __nv_bfloat16 g_Xl[(size_t)NPAD*D_DIM];
__device__ __align__(16) __nv_bfloat16 g_Hh[(size_t)NPAD*DFF];
__device__ __align__(16) __nv_bfloat16 g_Hl[(size_t)NPAD*DFF];
__device__ __align__(16) __nv_bfloat16 g_wh[2][(size_t)E_NUM*D_DIM*DFF];  // [e][n][k], hi
__device__ __align__(16) __nv_bfloat16 g_wl[2][(size_t)E_NUM*D_DIM*DFF];  // [e][n][k], lo
__device__ __align__(16) float g_Y[(size_t)NFLAT*D_DIM];

// ---------------- helpers ----------------
__device__ __forceinline__ uint32_t smem_u32(const void* p) {
    uint32_t a;
    asm("{ .reg .u64 t; cvta.to.shared.u64 t, %1; cvt.u32.u64 %0, t; }" : "=r"(a) : "l"(p));
    return a;
}
#define CP16(dst, src) \
    asm volatile("cp.async.cg.shared.global [%0], [%1], 16;" :: "r"(dst), "l"(src) : "memory")
#define CP_COMMIT() asm volatile("cp.async.commit_group;" ::: "memory")
#define CP_WAIT(n)  asm volatile("cp.async.wait_group %0;" :: "n"(n) : "memory")

__device__ __forceinline__ void ldsm4(uint32_t* r, uint32_t addr) {
    asm volatile("ldmatrix.sync.aligned.m8n8.x4.shared.b16 {%0,%1,%2,%3}, [%4];"
        : "=r"(r[0]), "=r"(r[1]), "=r"(r[2]), "=r"(r[3]) : "r"(addr));
}
__device__ __forceinline__ void mma16816(float* c, const uint32_t* a, const uint32_t* b) {
    asm volatile(
        "mma.sync.aligned.m16n8k16.row.col.f32.bf16.bf16.f32 "
        "{%0,%1,%2,%3}, {%4,%5,%6,%7}, {%8,%9}, {%0,%1,%2,%3};"
        : "+f"(c[0]), "+f"(c[1]), "+f"(c[2]), "+f"(c[3])
        : "r"(a[0]), "r"(a[1]), "r"(a[2]), "r"(a[3]), "r"(b[0]), "r"(b[1]));
}

// ---------------- gating: logits = X @ Wg + bg, then top-2 (proven) ----------------
__global__ void gate_kernel(const float* __restrict__ X,
                            const float* __restrict__ Wg,
                            const float* __restrict__ bg) {
    __shared__ float Xs[32][132];
    __shared__ float Wgs[32][36];
    __shared__ float lg[128][33];
    __shared__ float bgs[32];

    int tid = threadIdx.x;
    int t0  = blockIdx.x * 128;
    if (tid < 32) bgs[tid] = bg[tid];

    int tr = tid & 31;
    int te = tid >> 5;
    float acc[4][4];
#pragma unroll
    for (int i = 0; i < 4; i++)
#pragma unroll
        for (int j = 0; j < 4; j++) acc[i][j] = 0.f;

    for (int k0 = 0; k0 < D_DIM; k0 += 32) {
#pragma unroll
        for (int i = 0; i < 16; i++) {
            int lin = tid + i * 256;
            int r = lin >> 5, c = lin & 31;
            Xs[c][r] = X[(size_t)(t0 + r) * D_DIM + k0 + c];
        }
#pragma unroll
        for (int i = 0; i < 4; i++) {
            int lin = tid + i * 256;
            int r = lin >> 5, c = lin & 31;
            Wgs[r][c] = Wg[(size_t)(k0 + r) * E_NUM + c];
        }
        __syncthreads();
#pragma unroll
        for (int kk = 0; kk < 32; kk++) {
            float4 a4 = *(const float4*)&Xs[kk][tr * 4];
            float4 b4 = *(const float4*)&Wgs[kk][te * 4];
            float av[4] = {a4.x, a4.y, a4.z, a4.w};
            float bv[4] = {b4.x, b4.y, b4.z, b4.w};
#pragma unroll
            for (int i = 0; i < 4; i++)
#pragma unroll
                for (int j = 0; j < 4; j++) acc[i][j] += av[i] * bv[j];
        }
        __syncthreads();
    }
#pragma unroll
    for (int i = 0; i < 4; i++)
#pragma unroll
        for (int j = 0; j < 4; j++)
            lg[tr * 4 + i][te * 4 + j] = acc[i][j] + bgs[te * 4 + j];
    __syncthreads();

    if (tid < 128) {
        int t = t0 + tid;
        float v1 = -INFINITY; int i1 = 0;
        for (int e = 0; e < 32; e++) { float v = lg[tid][e]; if (v > v1) { v1 = v; i1 = e; } }
        float v2 = -INFINITY; int i2 = 0;
        for (int e = 0; e < 32; e++) {
            if (e == i1) continue;
            float v = lg[tid][e]; if (v > v2) { v2 = v; i2 = e; }
        }
        g_top2[t * 2]     = i1;
        g_top2[t * 2 + 1] = i2;
    }
}

// ---------------- stage A: per-segment expert histogram ----------------
__global__ void seg_hist_kernel() {
    __shared__ int cnt[E_NUM];
    int tid = threadIdx.x, s = blockIdx.x;
    if (tid < E_NUM) cnt[tid] = 0;
    __syncthreads();
    atomicAdd(&cnt[g_top2[s * 256 + tid]], 1);
    __syncthreads();
    if (tid < E_NUM) g_segcnt[tid * SEGS + s] = cnt[tid];
}

// ---------------- stage B: offsets + per-(expert,segment) bases ----------------
__global__ void seg_scan_kernel() {
    __shared__ int tot[E_NUM];
    int e = threadIdx.x;
    if (e < E_NUM) {
        int sum = 0;
        for (int s = 0; s < SEGS; ++s) sum += g_segcnt[e * SEGS + s];
        tot[e] = sum;
    }
    __syncthreads();
    if (e == 0) {
        int run = 0;
        for (int i = 0; i < E_NUM; ++i) { g_offsets[i] = run; run += tot[i]; }
        g_offsets[E_NUM] = run;
    }
    __syncthreads();
    if (e < E_NUM) {
        int run = g_offsets[e];
        for (int s = 0; s < SEGS; ++s) { g_segbase[e * SEGS + s] = run; run += g_segcnt[e * SEGS + s]; }
    }
}

// ---------------- stage C: stable scatter via warp ballots ----------------
__global__ void scatter_kernel() {
    __shared__ int wcnt[8][E_NUM];
    int tid = threadIdx.x, s = blockIdx.x;
    int w = tid >> 5, lane = tid & 31;
    wcnt[w][lane] = 0;
    __syncthreads();
    int f = s * 256 + tid;
    int e = g_top2[f];
    unsigned peers = __match_any_sync(0xffffffffu, e);
    unsigned lt = peers & ((1u << lane) - 1u);
    int rank = __popc(lt);
    if (lt == 0) wcnt[w][e] = __popc(peers);   // one leader per (warp, expert)
    __syncthreads();
    int base = g_segbase[e * SEGS + s] + rank;
#pragma unroll
    for (int w2 = 0; w2 < 8; ++w2) if (w2 < w) base += wcnt[w2][e];
    g_disp[base] = f;
}

// ---------------- weight transpose + bf16 hi/lo split: [e][k][n] -> [e][n][k] ----------------
// 64x64 tiles; coalesced fp32 loads, smem transpose, coalesced bf162 stores.
// Each of 256 threads: 4 n-rows x 2 bf162 pairs (16 lanes x 2 pairs = 32 pairs = 64 k). q < 2!
__global__ void convert_w_kernel(const float* __restrict__ w1, const float* __restrict__ w2) {
    __shared__ float t[64][65];
    int z = blockIdx.z;
    int widx = z >> 5, e = z & 31;
    const float* W = (widx ? w2 : w1) + (size_t)e * D_DIM * DFF;
    __nv_bfloat16* Oh = g_wh[widx] + (size_t)e * D_DIM * DFF;
    __nv_bfloat16* Ol = g_wl[widx] + (size_t)e * D_DIM * DFF;
    int k0 = blockIdx.x * 64, n0 = blockIdx.y * 64;
    int tid = threadIdx.x;
#pragma unroll
    for (int p = 0; p < 16; ++p) {
        int lin = tid + p * 256;
        int k = lin >> 6, n = lin & 63;
        t[k][n] = W[(size_t)(k0 + k) * 1024 + n0 + n];
    }
    __syncthreads();
    int k2 = tid & 15;           // 16 lanes cover 64 k values as 2 pairs each
    int nb = tid >> 4;           // 0..15
#pragma unroll
    for (int r = 0; r < 4; ++r) {
        int n = nb + r * 16;
        size_t rowo = (size_t)(n0 + n) * 1024 + k0;
#pragma unroll
        for (int q = 0; q < 2; ++q) {            // FIXED: was q<4 -> wrote k up to 126 (OOB)
            int k = k2 * 2 + q * 32;             // k in [0,62], within 64-wide tile
            float v0 = t[k][n], v1 = t[k + 1][n];
            __nv_bfloat16 h0 = __float2bfloat16(v0), h1 = __float2bfloat16(v1);
            *(__nv_bfloat162*)&Oh[rowo + k] = __halves2bfloat162(h0, h1);
            *(__nv_bfloat162*)&Ol[rowo + k] = __halves2bfloat162(
                __float2bfloat16(v0 - __bfloat162float(h0)),
                __float2bfloat16(v1 - __bfloat162float(h1)));
        }
    }
}

// ---------------- gather dispatched rows + bf16 hi/lo split ----------------
__global__ void gather_split_kernel(const float* __restrict__ X) {
    int g = blockIdx.x * 256 + threadIdx.x;   // per float4
    int r = g >> 8, c4 = g & 255;
    int tok = g_disp[r] >> 1;
    float4 v = ((const float4*)X)[(size_t)tok * 256 + c4];
    __nv_bfloat16 hx = __float2bfloat16(v.x), hy = __float2bfloat16(v.y);
    __nv_bfloat16 hz = __float2bfloat16(v.z), hw = __float2bfloat16(v.w);
    __nv_bfloat162* H2 = (__nv_bfloat162*)g_Xh;
    __nv_bfloat162* L2 = (__nv_bfloat162*)g_Xl;
    size_t o = (size_t)r * 512 + c4 * 2;
    H2[o]     = __halves2bfloat162(hx, hy);
    H2[o + 1] = __halves2bfloat162(hz, hw);
    L2[o]     = __halves2bfloat162(__float2bfloat16(v.x - __bfloat162float(hx)),
                                   __float2bfloat16(v.y - __bfloat162float(hy)));
    L2[o + 1] = __halves2bfloat162(__float2bfloat16(v.z - __bfloat162float(hz)),
                                   __float2bfloat16(v.w - __bfloat162float(hw)));
}

// ---------------- warp-MMA grouped GEMM (bf16 hi/lo split, cp.async + ldmatrix) ----------------
// block tile M=128 x N=128, K chunk=32 (NC=32), 8 warps (2M x 4N), warp tile 64x32.
// smem buffer (40960 B): Ah[128][80B] | Al | Bh[128][80B] | Bl
#define MAT_BYTES 10240
#define BUF_BYTES 40960
#define SMEM_DYN  (2*BUF_BYTES)
#define NC 32

__device__ __forceinline__ void fill_cp(uint32_t sbuf, const char* Ah, const char* Al,
                                        const char* Bh, const char* Bl, int kc, int tid) {
    int kbyte = kc * 64;
#pragma unroll
    for (int half = 0; half < 2; ++half) {
        int idx = tid + half * 256;          // 0..511
        int row = idx >> 2;
        int sg  = (idx & 3) * 16;
        uint32_t dst = sbuf + row * 80 + sg;
        size_t src = (size_t)row * 2048 + kbyte + sg;
        CP16(dst,                 Ah + src);
        CP16(dst + MAT_BYTES,     Al + src);
        CP16(dst + 2 * MAT_BYTES, Bh + src);
        CP16(dst + 3 * MAT_BYTES, Bl + src);
    }
}

__global__ void __launch_bounds__(256)
gemm_mma(int phase, const float* __restrict__ bias1, const float* __restrict__ bias2) {
    int e   = blockIdx.z;
    int off = g_offsets[e];
    int cnt = g_offsets[e + 1] - off;
    int row0 = blockIdx.y * 128;
    if (row0 >= cnt) return;
    int n0 = blockIdx.x * 128;

    extern __shared__ char dsm[];
    uint32_t sb = smem_u32(dsm);

    int tid = threadIdx.x, wid = tid >> 5, lane = tid & 31;
    int g = lane >> 2, tig = lane & 3;
    int m0w = (wid & 1) * 64;        // warp M base in tile
    int n0w = (wid >> 1) * 32;       // warp N base in tile

    // ldmatrix lane offsets (80 B row stride; conflict-free: row offsets mod 128B all distinct)
    uint32_t aoff = (uint32_t)((m0w + (lane & 15)) * 80 + ((lane >> 4) << 4));
    uint32_t boff = (uint32_t)((n0w + ((lane >> 4) << 3) + (lane & 7)) * 80 + (((lane >> 3) & 1) << 4));

    const char* Ah = (const char*)((phase ? g_Hh : g_Xh) + (size_t)(off + row0) * 1024);
    const char* Al = (const char*)((phase ? g_Hl : g_Xl) + (size_t)(off + row0) * 1024);
    const char* Bh = (const char*)(g_wh[phase] + ((size_t)e * 1024 + n0) * 1024);
    const char* Bl = (const char*)(g_wl[phase] + ((size_t)e * 1024 + n0) * 1024);
    const float* bias = (phase ? bias2 : bias1) + e * 1024;

    float acc[4][4][4];
#pragma unroll
    for (int mt = 0; mt < 4; mt++)
#pragma unroll
        for (int nt = 0; nt < 4; nt++)
#pragma unroll
            for (int q = 0; q < 4; q++) acc[mt][nt][q] = 0.f;

    fill_cp(sb, Ah, Al, Bh, Bl, 0, tid);
    CP_COMMIT();

    for (int c = 0; c < NC; ++c) {
        if (c + 1 < NC) {
            fill_cp(sb + ((c + 1) & 1) * BUF_BYTES, Ah, Al, Bh, Bl, c + 1, tid);
            CP_COMMIT();
            CP_WAIT(1);
        } else {
            CP_WAIT(0);
        }
        __syncthreads();

        uint32_t abuf = sb + (c & 1) * BUF_BYTES;
        uint32_t bbuf = abuf + 2 * MAT_BYTES;
#pragma unroll
        for (int ks = 0; ks < 2; ++ks) {
            uint32_t kso = ks * 32;
            uint32_t bh[4][2], bl[4][2];
            ldsm4(&bh[0][0], bbuf + boff + kso);
            ldsm4(&bh[2][0], bbuf + boff + kso + 1280);
            ldsm4(&bl[0][0], bbuf + boff + kso + MAT_BYTES);
            ldsm4(&bl[2][0], bbuf + boff + kso + MAT_BYTES + 1280);
#pragma unroll
            for (int mt = 0; mt < 4; mt++) {
                uint32_t ah[4], al[4];
                ldsm4(ah, abuf + aoff + kso + mt * 1280);
                ldsm4(al, abuf + aoff + kso + mt * 1280 + MAT_BYTES);
#pragma unroll
                for (int nt = 0; nt < 4; nt++) {
                    mma16816(acc[mt][nt], ah, bh[nt]);
                    mma16816(acc[mt][nt], ah, bl[nt]);
                    mma16816(acc[mt][nt], al, bh[nt]);
                }
            }
        }
        __syncthreads();
    }

    // epilogue: +bias, (gelu + bf16 split) or fp32 store
#pragma unroll
    for (int mt = 0; mt < 4; mt++) {
#pragma unroll
        for (int rh = 0; rh < 2; rh++) {
            int m = m0w + mt * 16 + g + rh * 8;
            if (row0 + m >= cnt) continue;
            size_t srow = (size_t)(off + row0 + m);
#pragma unroll
            for (int nt = 0; nt < 4; nt++) {
                int n = n0 + n0w + nt * 8 + 2 * tig;
                float v0 = acc[mt][nt][rh * 2]     + bias[n];
                float v1 = acc[mt][nt][rh * 2 + 1] + bias[n + 1];
                if (phase == 0) {
                    v0 = 0.5f * v0 * (1.0f + erff(v0 * 0.7071067811865475f));
                    v1 = 0.5f * v1 * (1.0f + erff(v1 * 0.7071067811865475f));
                    __nv_bfloat16 h0 = __float2bfloat16(v0);
                    __nv_bfloat16 h1 = __float2bfloat16(v1);
                    *(__nv_bfloat162*)&g_Hh[srow * 1024 + n] = __halves2bfloat162(h0, h1);
                    *(__nv_bfloat162*)&g_Hl[srow * 1024 + n] = __halves2bfloat162(
                        __float2bfloat16(v0 - __bfloat162float(h0)),
                        __float2bfloat16(v1 - __bfloat162float(h1)));
                } else {
                    *(float2*)&g_Y[srow * 1024 + n] = make_float2(v0, v1);
                }
            }
        }
    }
}

// ---------------- pair reduce: out[j] = Y[2j] + Y[2j+1] ----------------
__global__ void reduce_kernel(float* __restrict__ out) {
    int i = blockIdx.x * 256 + threadIdx.x;
    const int n4pr = D_DIM / 4;
    int total = B_TOK * n4pr;
    if (i < total) {
        const float4* Y4 = (const float4*)g_Y;
        float4* O4 = (float4*)out;
        int j  = i / n4pr;
        int n4 = i - j * n4pr;
        float4 a = Y4[(size_t)(2 * j) * n4pr + n4];
        float4 b = Y4[(size_t)(2 * j + 1) * n4pr + n4];
        O4[i] = make_float4(a.x + b.x, a.y + b.y, a.z + b.z, a.w + b.w);
    }
}

__global__ void idx_kernel(float* __restrict__ out) {
    int i = blockIdx.x * 256 + threadIdx.x;
    if (i < NFLAT) out[(size_t)B_TOK * D_DIM + i] = (float)g_top2[i];
}

// ---------------- launch ----------------
extern "C" void kernel_launch(void* const* d_in, const int* in_sizes, int n_in,
                              void* d_out, int out_size) {
    const float* X  = (const float*)d_in[0];
    const float* Wg = (const float*)d_in[1];
    const float* bg = (const float*)d_in[2];
    const float* w1 = (const float*)d_in[3];
    const float* b1 = (const float*)d_in[4];
    const float* w2 = (const float*)d_in[5];
    const float* b2 = (const float*)d_in[6];
    float* out = (float*)d_out;

    cudaFuncSetAttribute(gemm_mma, cudaFuncAttributeMaxDynamicSharedMemorySize, SMEM_DYN);

    convert_w_kernel<<<dim3(16, 16, 64), 256>>>(w1, w2);
    gate_kernel<<<B_TOK / 128, 256>>>(X, Wg, bg);
    seg_hist_kernel<<<SEGS, 256>>>();
    seg_scan_kernel<<<1, 256>>>();
    scatter_kernel<<<SEGS, 256>>>();
    gather_split_kernel<<<NFLAT, 256>>>(X);

    dim3 ggrid(DFF / 128, NFLAT / 128, E_NUM);   // empty tiles early-exit
    gemm_mma<<<ggrid, 256, SMEM_DYN>>>(0, b1, b2);
    gemm_mma<<<ggrid, 256, SMEM_DYN>>>(1, b1, b2);

    reduce_kernel<<<(B_TOK * (D_DIM / 4) + 255) / 256, 256>>>(out);
    if (out_size >= B_TOK * D_DIM + NFLAT)
        idx_kernel<<<(NFLAT + 255) / 256, 256>>>(out);
}

// round 13
// speedup vs baseline: 1.1701x; 1.1701x over previous
#include <cuda_runtime.h>
#include <cuda_bf16.h>
#include <math.h>
#include <stdint.h>

#define B_TOK 8192
#define D_DIM 1024
#define DFF   1024
#define E_NUM 32
#define NFLAT (B_TOK*2)
#define NPAD  (NFLAT+128)
#define SEGS  64            // NFLAT / 256

// ---------------- scratch (static device globals; no allocation) ----------------
__device__ int   g_top2[NFLAT];
__device__ int   g_offsets[E_NUM+1];
__device__ int   g_disp[NFLAT];
__device__ int   g_segcnt[E_NUM*SEGS];
__device__ int   g_segbase[E_NUM*SEGS];
__device__ __align__(16) __nv_bfloat16 g_Xh[(size_t)NPAD*D_DIM];
__device__ __align__(16) __nv_bfloat16 g_Xl[(size_t)NPAD*D_DIM];
__device__ __align__(16) __nv_bfloat16 g_Hh[(size_t)NPAD*DFF];
__device__ __align__(16) __nv_bfloat16 g_Hl[(size_t)NPAD*DFF];
__device__ __align__(16) __nv_bfloat16 g_wh[2][(size_t)E_NUM*D_DIM*DFF];  // [e][n][k], hi
__device__ __align__(16) __nv_bfloat16 g_wl[2][(size_t)E_NUM*D_DIM*DFF];  // [e][n][k], lo
__device__ __align__(16) float g_Y[(size_t)NFLAT*D_DIM];

// ---------------- helpers ----------------
__device__ __forceinline__ uint32_t smem_u32(const void* p) {
    uint32_t a;
    asm("{ .reg .u64 t; cvta.to.shared.u64 t, %1; cvt.u32.u64 %0, t; }" : "=r"(a) : "l"(p));
    return a;
}
#define CP16(dst, src) \
    asm volatile("cp.async.cg.shared.global [%0], [%1], 16;" :: "r"(dst), "l"(src) : "memory")
#define CP_COMMIT() asm volatile("cp.async.commit_group;" ::: "memory")
#define CP_WAIT(n)  asm volatile("cp.async.wait_group %0;" :: "n"(n) : "memory")

__device__ __forceinline__ void ldsm4(uint32_t* r, uint32_t addr) {
    asm volatile("ldmatrix.sync.aligned.m8n8.x4.shared.b16 {%0,%1,%2,%3}, [%4];"
        : "=r"(r[0]), "=r"(r[1]), "=r"(r[2]), "=r"(r[3]) : "r"(addr));
}
__device__ __forceinline__ void mma16816(float* c, const uint32_t* a, const uint32_t* b) {
    asm volatile(
        "mma.sync.aligned.m16n8k16.row.col.f32.bf16.bf16.f32 "
        "{%0,%1,%2,%3}, {%4,%5,%6,%7}, {%8,%9}, {%0,%1,%2,%3};"
        : "+f"(c[0]), "+f"(c[1]), "+f"(c[2]), "+f"(c[3])
        : "r"(a[0]), "r"(a[1]), "r"(a[2]), "r"(a[3]), "r"(b[0]), "r"(b[1]));
}

// ---------------- gating: logits = X @ Wg + bg, then top-2 (proven) ----------------
__global__ void gate_kernel(const float* __restrict__ X,
                            const float* __restrict__ Wg,
                            const float* __restrict__ bg) {
    __shared__ float Xs[32][132];
    __shared__ float Wgs[32][36];
    __shared__ float lg[128][33];
    __shared__ float bgs[32];

    int tid = threadIdx.x;
    int t0  = blockIdx.x * 128;
    if (tid < 32) bgs[tid] = bg[tid];

    int tr = tid & 31;
    int te = tid >> 5;
    float acc[4][4];
#pragma unroll
    for (int i = 0; i < 4; i++)
#pragma unroll
        for (int j = 0; j < 4; j++) acc[i][j] = 0.f;

    for (int k0 = 0; k0 < D_DIM; k0 += 32) {
#pragma unroll
        for (int i = 0; i < 16; i++) {
            int lin = tid + i * 256;
            int r = lin >> 5, c = lin & 31;
            Xs[c][r] = X[(size_t)(t0 + r) * D_DIM + k0 + c];
        }
#pragma unroll
        for (int i = 0; i < 4; i++) {
            int lin = tid + i * 256;
            int r = lin >> 5, c = lin & 31;
            Wgs[r][c] = Wg[(size_t)(k0 + r) * E_NUM + c];
        }
        __syncthreads();
#pragma unroll
        for (int kk = 0; kk < 32; kk++) {
            float4 a4 = *(const float4*)&Xs[kk][tr * 4];
            float4 b4 = *(const float4*)&Wgs[kk][te * 4];
            float av[4] = {a4.x, a4.y, a4.z, a4.w};
            float bv[4] = {b4.x, b4.y, b4.z, b4.w};
#pragma unroll
            for (int i = 0; i < 4; i++)
#pragma unroll
                for (int j = 0; j < 4; j++) acc[i][j] += av[i] * bv[j];
        }
        __syncthreads();
    }
#pragma unroll
    for (int i = 0; i < 4; i++)
#pragma unroll
        for (int j = 0; j < 4; j++)
            lg[tr * 4 + i][te * 4 + j] = acc[i][j] + bgs[te * 4 + j];
    __syncthreads();

    if (tid < 128) {
        int t = t0 + tid;
        float v1 = -INFINITY; int i1 = 0;
        for (int e = 0; e < 32; e++) { float v = lg[tid][e]; if (v > v1) { v1 = v; i1 = e; } }
        float v2 = -INFINITY; int i2 = 0;
        for (int e = 0; e < 32; e++) {
            if (e == i1) continue;
            float v = lg[tid][e]; if (v > v2) { v2 = v; i2 = e; }
        }
        g_top2[t * 2]     = i1;
        g_top2[t * 2 + 1] = i2;
    }
}

// ---------------- stage A: per-segment expert histogram ----------------
__global__ void seg_hist_kernel() {
    __shared__ int cnt[E_NUM];
    int tid = threadIdx.x, s = blockIdx.x;
    if (tid < E_NUM) cnt[tid] = 0;
    __syncthreads();
    atomicAdd(&cnt[g_top2[s * 256 + tid]], 1);
    __syncthreads();
    if (tid < E_NUM) g_segcnt[tid * SEGS + s] = cnt[tid];
}

// ---------------- stage B: offsets + per-(expert,segment) bases (warp-parallel) ----------------
// 1024 threads = 32 warps; warp w owns expert w. Warp-shfl scans replace serial loops.
__global__ void seg_scan_kernel() {
    __shared__ int tot[E_NUM];
    int w = threadIdx.x >> 5, lane = threadIdx.x & 31;
    int c0 = g_segcnt[w * SEGS + lane];        // segments 0..31
    int c1 = g_segcnt[w * SEGS + 32 + lane];   // segments 32..63
    int s0 = c0, s1 = c1;
#pragma unroll
    for (int o = 1; o < 32; o <<= 1) {
        int v0 = __shfl_up_sync(0xffffffffu, s0, o);
        int v1 = __shfl_up_sync(0xffffffffu, s1, o);
        if (lane >= o) { s0 += v0; s1 += v1; }
    }
    int t0 = __shfl_sync(0xffffffffu, s0, 31);     // sum of first 32 segments
    if (lane == 31) tot[w] = s0 + s1;
    __syncthreads();
    if (w == 0) {
        int t = tot[lane];
        int sc = t;
#pragma unroll
        for (int o = 1; o < 32; o <<= 1) {
            int v = __shfl_up_sync(0xffffffffu, sc, o);
            if (lane >= o) sc += v;
        }
        g_offsets[lane] = sc - t;                  // exclusive
        if (lane == 31) g_offsets[32] = sc;
    }
    __syncthreads();
    int base = g_offsets[w];
    g_segbase[w * SEGS + lane]      = base + s0 - c0;
    g_segbase[w * SEGS + 32 + lane] = base + t0 + s1 - c1;
}

// ---------------- stage C: stable scatter via warp ballots ----------------
__global__ void scatter_kernel() {
    __shared__ int wcnt[8][E_NUM];
    int tid = threadIdx.x, s = blockIdx.x;
    int w = tid >> 5, lane = tid & 31;
    wcnt[w][lane] = 0;
    __syncthreads();
    int f = s * 256 + tid;
    int e = g_top2[f];
    unsigned peers = __match_any_sync(0xffffffffu, e);
    unsigned lt = peers & ((1u << lane) - 1u);
    int rank = __popc(lt);
    if (lt == 0) wcnt[w][e] = __popc(peers);   // one leader per (warp, expert)
    __syncthreads();
    int base = g_segbase[e * SEGS + s] + rank;
#pragma unroll
    for (int w2 = 0; w2 < 8; ++w2) if (w2 < w) base += wcnt[w2][e];
    g_disp[base] = f;
}

// ---------------- weight transpose + bf16 hi/lo split: [e][k][n] -> [e][n][k] ----------------
__global__ void convert_w_kernel(const float* __restrict__ w1, const float* __restrict__ w2) {
    __shared__ float t[64][65];
    int z = blockIdx.z;
    int widx = z >> 5, e = z & 31;
    const float* W = (widx ? w2 : w1) + (size_t)e * D_DIM * DFF;
    __nv_bfloat16* Oh = g_wh[widx] + (size_t)e * D_DIM * DFF;
    __nv_bfloat16* Ol = g_wl[widx] + (size_t)e * D_DIM * DFF;
    int k0 = blockIdx.x * 64, n0 = blockIdx.y * 64;
    int tid = threadIdx.x;
#pragma unroll
    for (int p = 0; p < 16; ++p) {
        int lin = tid + p * 256;
        int k = lin >> 6, n = lin & 63;
        t[k][n] = W[(size_t)(k0 + k) * 1024 + n0 + n];
    }
    __syncthreads();
    int k2 = tid & 15;
    int nb = tid >> 4;
#pragma unroll
    for (int r = 0; r < 4; ++r) {
        int n = nb + r * 16;
        size_t rowo = (size_t)(n0 + n) * 1024 + k0;
#pragma unroll
        for (int q = 0; q < 2; ++q) {
            int k = k2 * 2 + q * 32;
            float v0 = t[k][n], v1 = t[k + 1][n];
            __nv_bfloat16 h0 = __float2bfloat16(v0), h1 = __float2bfloat16(v1);
            *(__nv_bfloat162*)&Oh[rowo + k] = __halves2bfloat162(h0, h1);
            *(__nv_bfloat162*)&Ol[rowo + k] = __halves2bfloat162(
                __float2bfloat16(v0 - __bfloat162float(h0)),
                __float2bfloat16(v1 - __bfloat162float(h1)));
        }
    }
}

// ---------------- gather dispatched rows + bf16 hi/lo split ----------------
__global__ void gather_split_kernel(const float* __restrict__ X) {
    int g = blockIdx.x * 256 + threadIdx.x;   // per float4
    int r = g >> 8, c4 = g & 255;
    int tok = g_disp[r] >> 1;
    float4 v = ((const float4*)X)[(size_t)tok * 256 + c4];
    __nv_bfloat16 hx = __float2bfloat16(v.x), hy = __float2bfloat16(v.y);
    __nv_bfloat16 hz = __float2bfloat16(v.z), hw = __float2bfloat16(v.w);
    __nv_bfloat162* H2 = (__nv_bfloat162*)g_Xh;
    __nv_bfloat162* L2 = (__nv_bfloat162*)g_Xl;
    size_t o = (size_t)r * 512 + c4 * 2;
    H2[o]     = __halves2bfloat162(hx, hy);
    H2[o + 1] = __halves2bfloat162(hz, hw);
    L2[o]     = __halves2bfloat162(__float2bfloat16(v.x - __bfloat162float(hx)),
                                   __float2bfloat16(v.y - __bfloat162float(hy)));
    L2[o + 1] = __halves2bfloat162(__float2bfloat16(v.z - __bfloat162float(hz)),
                                   __float2bfloat16(v.w - __bfloat162float(hw)));
}

// ---------------- warp-MMA grouped GEMM (bf16 hi/lo split, cp.async + ldmatrix) ----------------
// block tile M=128 x N=128, K chunk=32 (NC=32), 8 warps (2M x 4N), warp tile 64x32.
// smem buffer (40960 B): Ah[128][80B] | Al | Bh[128][80B] | Bl
// __launch_bounds__(256, 2): cap regs at 128 -> 2 CTAs/SM so MMA of one hides loads of the other.
#define MAT_BYTES 10240
#define BUF_BYTES 40960
#define SMEM_DYN  (2*BUF_BYTES)
#define NC 32

__device__ __forceinline__ void fill_cp(uint32_t sbuf, const char* Ah, const char* Al,
                                        const char* Bh, const char* Bl, int kc, int tid) {
    int kbyte = kc * 64;
#pragma unroll
    for (int half = 0; half < 2; ++half) {
        int idx = tid + half * 256;          // 0..511
        int row = idx >> 2;
        int sg  = (idx & 3) * 16;
        uint32_t dst = sbuf + row * 80 + sg;
        size_t src = (size_t)row * 2048 + kbyte + sg;
        CP16(dst,                 Ah + src);
        CP16(dst + MAT_BYTES,     Al + src);
        CP16(dst + 2 * MAT_BYTES, Bh + src);
        CP16(dst + 3 * MAT_BYTES, Bl + src);
    }
}

__global__ void __launch_bounds__(256, 2)
gemm_mma(int phase, const float* __restrict__ bias1, const float* __restrict__ bias2) {
    int e   = blockIdx.z;
    int off = g_offsets[e];
    int cnt = g_offsets[e + 1] - off;
    int row0 = blockIdx.y * 128;
    if (row0 >= cnt) return;
    int n0 = blockIdx.x * 128;

    extern __shared__ char dsm[];
    uint32_t sb = smem_u32(dsm);

    int tid = threadIdx.x, wid = tid >> 5, lane = tid & 31;
    int g = lane >> 2, tig = lane & 3;
    int m0w = (wid & 1) * 64;        // warp M base in tile
    int n0w = (wid >> 1) * 32;       // warp N base in tile

    // ldmatrix lane offsets (80 B row stride; conflict-free: row offsets mod 128B all distinct)
    uint32_t aoff = (uint32_t)((m0w + (lane & 15)) * 80 + ((lane >> 4) << 4));
    uint32_t boff = (uint32_t)((n0w + ((lane >> 4) << 3) + (lane & 7)) * 80 + (((lane >> 3) & 1) << 4));

    const char* Ah = (const char*)((phase ? g_Hh : g_Xh) + (size_t)(off + row0) * 1024);
    const char* Al = (const char*)((phase ? g_Hl : g_Xl) + (size_t)(off + row0) * 1024);
    const char* Bh = (const char*)(g_wh[phase] + ((size_t)e * 1024 + n0) * 1024);
    const char* Bl = (const char*)(g_wl[phase] + ((size_t)e * 1024 + n0) * 1024);
    const float* bias = (phase ? bias2 : bias1) + e * 1024;

    float acc[4][4][4];
#pragma unroll
    for (int mt = 0; mt < 4; mt++)
#pragma unroll
        for (int nt = 0; nt < 4; nt++)
#pragma unroll
            for (int q = 0; q < 4; q++) acc[mt][nt][q] = 0.f;

    fill_cp(sb, Ah, Al, Bh, Bl, 0, tid);
    CP_COMMIT();

    for (int c = 0; c < NC; ++c) {
        if (c + 1 < NC) {
            fill_cp(sb + ((c + 1) & 1) * BUF_BYTES, Ah, Al, Bh, Bl, c + 1, tid);
            CP_COMMIT();
            CP_WAIT(1);
        } else {
            CP_WAIT(0);
        }
        __syncthreads();

        uint32_t abuf = sb + (c & 1) * BUF_BYTES;
        uint32_t bbuf = abuf + 2 * MAT_BYTES;
#pragma unroll
        for (int ks = 0; ks < 2; ++ks) {
            uint32_t kso = ks * 32;
            uint32_t bh[4][2], bl[4][2];
            ldsm4(&bh[0][0], bbuf + boff + kso);
            ldsm4(&bh[2][0], bbuf + boff + kso + 1280);
            ldsm4(&bl[0][0], bbuf + boff + kso + MAT_BYTES);
            ldsm4(&bl[2][0], bbuf + boff + kso + MAT_BYTES + 1280);
#pragma unroll
            for (int mt = 0; mt < 4; mt++) {
                uint32_t ah[4], al[4];
                ldsm4(ah, abuf + aoff + kso + mt * 1280);
                ldsm4(al, abuf + aoff + kso + mt * 1280 + MAT_BYTES);
#pragma unroll
                for (int nt = 0; nt < 4; nt++) {
                    mma16816(acc[mt][nt], ah, bh[nt]);
                    mma16816(acc[mt][nt], ah, bl[nt]);
                    mma16816(acc[mt][nt], al, bh[nt]);
                }
            }
        }
        __syncthreads();
    }

    // epilogue: +bias, (gelu + bf16 split) or fp32 store
#pragma unroll
    for (int mt = 0; mt < 4; mt++) {
#pragma unroll
        for (int rh = 0; rh < 2; rh++) {
            int m = m0w + mt * 16 + g + rh * 8;
            if (row0 + m >= cnt) continue;
            size_t srow = (size_t)(off + row0 + m);
#pragma unroll
            for (int nt = 0; nt < 4; nt++) {
                int n = n0 + n0w + nt * 8 + 2 * tig;
                float v0 = acc[mt][nt][rh * 2]     + bias[n];
                float v1 = acc[mt][nt][rh * 2 + 1] + bias[n + 1];
                if (phase == 0) {
                    v0 = 0.5f * v0 * (1.0f + erff(v0 * 0.7071067811865475f));
                    v1 = 0.5f * v1 * (1.0f + erff(v1 * 0.7071067811865475f));
                    __nv_bfloat16 h0 = __float2bfloat16(v0);
                    __nv_bfloat16 h1 = __float2bfloat16(v1);
                    *(__nv_bfloat162*)&g_Hh[srow * 1024 + n] = __halves2bfloat162(h0, h1);
                    *(__nv_bfloat162*)&g_Hl[srow * 1024 + n] = __halves2bfloat162(
                        __float2bfloat16(v0 - __bfloat162float(h0)),
                        __float2bfloat16(v1 - __bfloat162float(h1)));
                } else {
                    *(float2*)&g_Y[srow * 1024 + n] = make_float2(v0, v1);
                }
            }
        }
    }
}

// ---------------- pair reduce: out[j] = Y[2j] + Y[2j+1] ----------------
__global__ void reduce_kernel(float* __restrict__ out) {
    int i = blockIdx.x * 256 + threadIdx.x;
    const int n4pr = D_DIM / 4;
    int total = B_TOK * n4pr;
    if (i < total) {
        const float4* Y4 = (const float4*)g_Y;
        float4* O4 = (float4*)out;
        int j  = i / n4pr;
        int n4 = i - j * n4pr;
        float4 a = Y4[(size_t)(2 * j) * n4pr + n4];
        float4 b = Y4[(size_t)(2 * j + 1) * n4pr + n4];
        O4[i] = make_float4(a.x + b.x, a.y + b.y, a.z + b.z, a.w + b.w);
    }
}

__global__ void idx_kernel(float* __restrict__ out) {
    int i = blockIdx.x * 256 + threadIdx.x;
    if (i < NFLAT) out[(size_t)B_TOK * D_DIM + i] = (float)g_top2[i];
}

// ---------------- launch ----------------
extern "C" void kernel_launch(void* const* d_in, const int* in_sizes, int n_in,
                              void* d_out, int out_size) {
    const float* X  = (const float*)d_in[0];
    const float* Wg = (const float*)d_in[1];
    const float* bg = (const float*)d_in[2];
    const float* w1 = (const float*)d_in[3];
    const float* b1 = (const float*)d_in[4];
    const float* w2 = (const float*)d_in[5];
    const float* b2 = (const float*)d_in[6];
    float* out = (float*)d_out;

    cudaFuncSetAttribute(gemm_mma, cudaFuncAttributeMaxDynamicSharedMemorySize, SMEM_DYN);

    convert_w_kernel<<<dim3(16, 16, 64), 256>>>(w1, w2);
    gate_kernel<<<B_TOK / 128, 256>>>(X, Wg, bg);
    seg_hist_kernel<<<SEGS, 256>>>();
    seg_scan_kernel<<<1, 1024>>>();
    scatter_kernel<<<SEGS, 256>>>();
    gather_split_kernel<<<NFLAT, 256>>>(X);

    dim3 ggrid(DFF / 128, NFLAT / 128, E_NUM);   // empty tiles early-exit
    gemm_mma<<<ggrid, 256, SMEM_DYN>>>(0, b1, b2);
    gemm_mma<<<ggrid, 256, SMEM_DYN>>>(1, b1, b2);

    reduce_kernel<<<(B_TOK * (D_DIM / 4) + 255) / 256, 256>>>(out);
    if (out_size >= B_TOK * D_DIM + NFLAT)
        idx_kernel<<<(NFLAT + 255) / 256, 256>>>(out);
}

// round 14
// speedup vs baseline: 2.2443x; 1.9181x over previous
#include <cuda_runtime.h>
#include <cuda_fp16.h>
#include <math.h>
#include <stdint.h>

#define B_TOK 8192
#define D_DIM 1024
#define DFF   1024
#define E_NUM 32
#define NFLAT (B_TOK*2)
#define NPAD  (NFLAT+128)
#define SEGS  64            // NFLAT / 256

// ---------------- scratch (static device globals; no allocation) ----------------
__device__ int   g_top2[NFLAT];
__device__ int   g_offsets[E_NUM+1];
__device__ int   g_disp[NFLAT];
__device__ int   g_segcnt[E_NUM*SEGS];
__device__ int   g_segbase[E_NUM*SEGS];
__device__ __align__(16) __half g_Xf[(size_t)NPAD*D_DIM];
__device__ __align__(16) __half g_Hf[(size_t)NPAD*DFF];
__device__ __align__(16) __half g_wf[2][(size_t)E_NUM*D_DIM*DFF];  // [e][n][k] fp16
__device__ __align__(16) float g_Y[(size_t)NFLAT*D_DIM];

// ---------------- helpers ----------------
__device__ __forceinline__ uint32_t smem_u32(const void* p) {
    uint32_t a;
    asm("{ .reg .u64 t; cvta.to.shared.u64 t, %1; cvt.u32.u64 %0, t; }" : "=r"(a) : "l"(p));
    return a;
}
#define CP16(dst, src) \
    asm volatile("cp.async.cg.shared.global [%0], [%1], 16;" :: "r"(dst), "l"(src) : "memory")
#define CP_COMMIT() asm volatile("cp.async.commit_group;" ::: "memory")
#define CP_WAIT(n)  asm volatile("cp.async.wait_group %0;" :: "n"(n) : "memory")

__device__ __forceinline__ void ldsm4(uint32_t* r, uint32_t addr) {
    asm volatile("ldmatrix.sync.aligned.m8n8.x4.shared.b16 {%0,%1,%2,%3}, [%4];"
        : "=r"(r[0]), "=r"(r[1]), "=r"(r[2]), "=r"(r[3]) : "r"(addr));
}
__device__ __forceinline__ void mma16816h(float* c, const uint32_t* a, const uint32_t* b) {
    asm volatile(
        "mma.sync.aligned.m16n8k16.row.col.f32.f16.f16.f32 "
        "{%0,%1,%2,%3}, {%4,%5,%6,%7}, {%8,%9}, {%0,%1,%2,%3};"
        : "+f"(c[0]), "+f"(c[1]), "+f"(c[2]), "+f"(c[3])
        : "r"(a[0]), "r"(a[1]), "r"(a[2]), "r"(a[3]), "r"(b[0]), "r"(b[1]));
}

// ---------------- gating: logits = X @ Wg + bg, then top-2 (proven) ----------------
__global__ void gate_kernel(const float* __restrict__ X,
                            const float* __restrict__ Wg,
                            const float* __restrict__ bg) {
    __shared__ float Xs[32][132];
    __shared__ float Wgs[32][36];
    __shared__ float lg[128][33];
    __shared__ float bgs[32];

    int tid = threadIdx.x;
    int t0  = blockIdx.x * 128;
    if (tid < 32) bgs[tid] = bg[tid];

    int tr = tid & 31;
    int te = tid >> 5;
    float acc[4][4];
#pragma unroll
    for (int i = 0; i < 4; i++)
#pragma unroll
        for (int j = 0; j < 4; j++) acc[i][j] = 0.f;

    for (int k0 = 0; k0 < D_DIM; k0 += 32) {
#pragma unroll
        for (int i = 0; i < 16; i++) {
            int lin = tid + i * 256;
            int r = lin >> 5, c = lin & 31;
            Xs[c][r] = X[(size_t)(t0 + r) * D_DIM + k0 + c];
        }
#pragma unroll
        for (int i = 0; i < 4; i++) {
            int lin = tid + i * 256;
            int r = lin >> 5, c = lin & 31;
            Wgs[r][c] = Wg[(size_t)(k0 + r) * E_NUM + c];
        }
        __syncthreads();
#pragma unroll
        for (int kk = 0; kk < 32; kk++) {
            float4 a4 = *(const float4*)&Xs[kk][tr * 4];
            float4 b4 = *(const float4*)&Wgs[kk][te * 4];
            float av[4] = {a4.x, a4.y, a4.z, a4.w};
            float bv[4] = {b4.x, b4.y, b4.z, b4.w};
#pragma unroll
            for (int i = 0; i < 4; i++)
#pragma unroll
                for (int j = 0; j < 4; j++) acc[i][j] += av[i] * bv[j];
        }
        __syncthreads();
    }
#pragma unroll
    for (int i = 0; i < 4; i++)
#pragma unroll
        for (int j = 0; j < 4; j++)
            lg[tr * 4 + i][te * 4 + j] = acc[i][j] + bgs[te * 4 + j];
    __syncthreads();

    if (tid < 128) {
        int t = t0 + tid;
        float v1 = -INFINITY; int i1 = 0;
        for (int e = 0; e < 32; e++) { float v = lg[tid][e]; if (v > v1) { v1 = v; i1 = e; } }
        float v2 = -INFINITY; int i2 = 0;
        for (int e = 0; e < 32; e++) {
            if (e == i1) continue;
            float v = lg[tid][e]; if (v > v2) { v2 = v; i2 = e; }
        }
        g_top2[t * 2]     = i1;
        g_top2[t * 2 + 1] = i2;
    }
}

// ---------------- stage A: per-segment expert histogram ----------------
__global__ void seg_hist_kernel() {
    __shared__ int cnt[E_NUM];
    int tid = threadIdx.x, s = blockIdx.x;
    if (tid < E_NUM) cnt[tid] = 0;
    __syncthreads();
    atomicAdd(&cnt[g_top2[s * 256 + tid]], 1);
    __syncthreads();
    if (tid < E_NUM) g_segcnt[tid * SEGS + s] = cnt[tid];
}

// ---------------- stage B: offsets + per-(expert,segment) bases (warp-parallel) ----------------
__global__ void seg_scan_kernel() {
    __shared__ int tot[E_NUM];
    int w = threadIdx.x >> 5, lane = threadIdx.x & 31;
    int c0 = g_segcnt[w * SEGS + lane];
    int c1 = g_segcnt[w * SEGS + 32 + lane];
    int s0 = c0, s1 = c1;
#pragma unroll
    for (int o = 1; o < 32; o <<= 1) {
        int v0 = __shfl_up_sync(0xffffffffu, s0, o);
        int v1 = __shfl_up_sync(0xffffffffu, s1, o);
        if (lane >= o) { s0 += v0; s1 += v1; }
    }
    int t0 = __shfl_sync(0xffffffffu, s0, 31);
    if (lane == 31) tot[w] = s0 + s1;
    __syncthreads();
    if (w == 0) {
        int t = tot[lane];
        int sc = t;
#pragma unroll
        for (int o = 1; o < 32; o <<= 1) {
            int v = __shfl_up_sync(0xffffffffu, sc, o);
            if (lane >= o) sc += v;
        }
        g_offsets[lane] = sc - t;
        if (lane == 31) g_offsets[32] = sc;
    }
    __syncthreads();
    int base = g_offsets[w];
    g_segbase[w * SEGS + lane]      = base + s0 - c0;
    g_segbase[w * SEGS + 32 + lane] = base + t0 + s1 - c1;
}

// ---------------- stage C: stable scatter via warp ballots ----------------
__global__ void scatter_kernel() {
    __shared__ int wcnt[8][E_NUM];
    int tid = threadIdx.x, s = blockIdx.x;
    int w = tid >> 5, lane = tid & 31;
    wcnt[w][lane] = 0;
    __syncthreads();
    int f = s * 256 + tid;
    int e = g_top2[f];
    unsigned peers = __match_any_sync(0xffffffffu, e);
    unsigned lt = peers & ((1u << lane) - 1u);
    int rank = __popc(lt);
    if (lt == 0) wcnt[w][e] = __popc(peers);
    __syncthreads();
    int base = g_segbase[e * SEGS + s] + rank;
#pragma unroll
    for (int w2 = 0; w2 < 8; ++w2) if (w2 < w) base += wcnt[w2][e];
    g_disp[base] = f;
}

// ---------------- weight transpose + fp16 convert: [e][k][n] -> [e][n][k] ----------------
__global__ void convert_w_kernel(const float* __restrict__ w1, const float* __restrict__ w2) {
    __shared__ float t[64][65];
    int z = blockIdx.z;
    int widx = z >> 5, e = z & 31;
    const float* W = (widx ? w2 : w1) + (size_t)e * D_DIM * DFF;
    __half* O = g_wf[widx] + (size_t)e * D_DIM * DFF;
    int k0 = blockIdx.x * 64, n0 = blockIdx.y * 64;
    int tid = threadIdx.x;
#pragma unroll
    for (int p = 0; p < 16; ++p) {
        int lin = tid + p * 256;
        int k = lin >> 6, n = lin & 63;
        t[k][n] = W[(size_t)(k0 + k) * 1024 + n0 + n];
    }
    __syncthreads();
    int k2 = tid & 15;
    int nb = tid >> 4;
#pragma unroll
    for (int r = 0; r < 4; ++r) {
        int n = nb + r * 16;
        size_t rowo = (size_t)(n0 + n) * 1024 + k0;
#pragma unroll
        for (int q = 0; q < 2; ++q) {
            int k = k2 * 2 + q * 32;
            *(__half2*)&O[rowo + k] = __floats2half2_rn(t[k][n], t[k + 1][n]);
        }
    }
}

// ---------------- gather dispatched rows + fp16 convert ----------------
__global__ void gather_half_kernel(const float* __restrict__ X) {
    int g = blockIdx.x * 256 + threadIdx.x;   // per float4
    int r = g >> 8, c4 = g & 255;
    int tok = g_disp[r] >> 1;
    float4 v = ((const float4*)X)[(size_t)tok * 256 + c4];
    __half2* H2 = (__half2*)g_Xf;
    size_t o = (size_t)r * 512 + c4 * 2;
    H2[o]     = __floats2half2_rn(v.x, v.y);
    H2[o + 1] = __floats2half2_rn(v.z, v.w);
}

// ---------------- warp-MMA grouped GEMM (fp16 single-pass, cp.async + ldmatrix) ----------------
// block tile M=128 x N=128, K chunk=64 (NC=16), 8 warps (2M x 4N), warp tile 64x32.
// smem per buffer: A[128 rows][144B] | B[128 rows][144B]  (row = 128B data + 16B pad)
#define ROW_S   144
#define BMAT_OFF (128*ROW_S)            // 18432
#define BUF_BYTES (2*128*ROW_S)         // 36864
#define SMEM_DYN  (2*BUF_BYTES)         // 73728 -> 2 CTAs/SM uses 147456 < 228KB
#define NC 16

__device__ __forceinline__ void fill_cp(uint32_t sbuf, const char* A, const char* B,
                                        int kc, int tid) {
    int kbyte = kc * 128;                // 64 fp16 = 128 B per chunk
#pragma unroll
    for (int i = 0; i < 4; ++i) {
        int idx = tid + i * 256;         // 0..1023
        int row = idx >> 3, sg = (idx & 7) * 16;
        uint32_t dst = sbuf + row * ROW_S + sg;
        size_t src = (size_t)row * 2048 + kbyte + sg;
        CP16(dst,            A + src);
        CP16(dst + BMAT_OFF, B + src);
    }
}

__global__ void __launch_bounds__(256, 2)
gemm_mma(int phase, const float* __restrict__ bias1, const float* __restrict__ bias2) {
    int e   = blockIdx.z;
    int off = g_offsets[e];
    int cnt = g_offsets[e + 1] - off;
    int row0 = blockIdx.y * 128;
    if (row0 >= cnt) return;
    int n0 = blockIdx.x * 128;

    extern __shared__ char dsm[];
    uint32_t sb = smem_u32(dsm);

    int tid = threadIdx.x, wid = tid >> 5, lane = tid & 31;
    int g = lane >> 2, tig = lane & 3;
    int m0w = (wid & 1) * 64;        // warp M base
    int n0w = (wid >> 1) * 32;       // warp N base

    // ldmatrix lane offsets (144 B row stride; 16r mod 128 distinct over 8 rows -> conflict-free)
    uint32_t aoff = (uint32_t)((m0w + (lane & 15)) * ROW_S + ((lane >> 4) << 4));
    uint32_t boff = (uint32_t)((n0w + ((lane >> 4) << 3) + (lane & 7)) * ROW_S + (((lane >> 3) & 1) << 4));

    const char* A = (const char*)((phase ? g_Hf : g_Xf) + (size_t)(off + row0) * 1024);
    const char* B = (const char*)(g_wf[phase] + ((size_t)e * 1024 + n0) * 1024);
    const float* bias = (phase ? bias2 : bias1) + e * 1024;

    float acc[4][4][4];
#pragma unroll
    for (int mt = 0; mt < 4; mt++)
#pragma unroll
        for (int nt = 0; nt < 4; nt++)
#pragma unroll
            for (int q = 0; q < 4; q++) acc[mt][nt][q] = 0.f;

    fill_cp(sb, A, B, 0, tid);
    CP_COMMIT();

    for (int c = 0; c < NC; ++c) {
        if (c + 1 < NC) {
            fill_cp(sb + ((c + 1) & 1) * BUF_BYTES, A, B, c + 1, tid);
            CP_COMMIT();
            CP_WAIT(1);
        } else {
            CP_WAIT(0);
        }
        __syncthreads();

        uint32_t abuf = sb + (c & 1) * BUF_BYTES;
        uint32_t bbuf = abuf + BMAT_OFF;
#pragma unroll
        for (int ks = 0; ks < 4; ++ks) {
            uint32_t kso = ks * 32;
            uint32_t bfr[4][2];
            ldsm4(&bfr[0][0], bbuf + boff + kso);            // nt0, nt1 (n0-15)
            ldsm4(&bfr[2][0], bbuf + boff + kso + 16 * ROW_S); // nt2, nt3 (n16-31)
#pragma unroll
            for (int mt = 0; mt < 4; mt++) {
                uint32_t afr[4];
                ldsm4(afr, abuf + aoff + kso + mt * 16 * ROW_S);
#pragma unroll
                for (int nt = 0; nt < 4; nt++)
                    mma16816h(acc[mt][nt], afr, bfr[nt]);
            }
        }
        __syncthreads();
    }

    // epilogue: +bias, (gelu -> fp16 H) or fp32 Y store
#pragma unroll
    for (int mt = 0; mt < 4; mt++) {
#pragma unroll
        for (int rh = 0; rh < 2; rh++) {
            int m = m0w + mt * 16 + g + rh * 8;
            if (row0 + m >= cnt) continue;
            size_t srow = (size_t)(off + row0 + m);
#pragma unroll
            for (int nt = 0; nt < 4; nt++) {
                int n = n0 + n0w + nt * 8 + 2 * tig;
                float v0 = acc[mt][nt][rh * 2]     + bias[n];
                float v1 = acc[mt][nt][rh * 2 + 1] + bias[n + 1];
                if (phase == 0) {
                    v0 = 0.5f * v0 * (1.0f + erff(v0 * 0.7071067811865475f));
                    v1 = 0.5f * v1 * (1.0f + erff(v1 * 0.7071067811865475f));
                    *(__half2*)&g_Hf[srow * 1024 + n] = __floats2half2_rn(v0, v1);
                } else {
                    *(float2*)&g_Y[srow * 1024 + n] = make_float2(v0, v1);
                }
            }
        }
    }
}

// ---------------- pair reduce: out[j] = Y[2j] + Y[2j+1] ----------------
__global__ void reduce_kernel(float* __restrict__ out) {
    int i = blockIdx.x * 256 + threadIdx.x;
    const int n4pr = D_DIM / 4;
    int total = B_TOK * n4pr;
    if (i < total) {
        const float4* Y4 = (const float4*)g_Y;
        float4* O4 = (float4*)out;
        int j  = i / n4pr;
        int n4 = i - j * n4pr;
        float4 a = Y4[(size_t)(2 * j) * n4pr + n4];
        float4 b = Y4[(size_t)(2 * j + 1) * n4pr + n4];
        O4[i] = make_float4(a.x + b.x, a.y + b.y, a.z + b.z, a.w + b.w);
    }
}

__global__ void idx_kernel(float* __restrict__ out) {
    int i = blockIdx.x * 256 + threadIdx.x;
    if (i < NFLAT) out[(size_t)B_TOK * D_DIM + i] = (float)g_top2[i];
}

// ---------------- launch ----------------
extern "C" void kernel_launch(void* const* d_in, const int* in_sizes, int n_in,
                              void* d_out, int out_size) {
    const float* X  = (const float*)d_in[0];
    const float* Wg = (const float*)d_in[1];
    const float* bg = (const float*)d_in[2];
    const float* w1 = (const float*)d_in[3];
    const float* b1 = (const float*)d_in[4];
    const float* w2 = (const float*)d_in[5];
    const float* b2 = (const float*)d_in[6];
    float* out = (float*)d_out;

    cudaFuncSetAttribute(gemm_mma, cudaFuncAttributeMaxDynamicSharedMemorySize, SMEM_DYN);

    convert_w_kernel<<<dim3(16, 16, 64), 256>>>(w1, w2);
    gate_kernel<<<B_TOK / 128, 256>>>(X, Wg, bg);
    seg_hist_kernel<<<SEGS, 256>>>();
    seg_scan_kernel<<<1, 1024>>>();
    scatter_kernel<<<SEGS, 256>>>();
    gather_half_kernel<<<NFLAT, 256>>>(X);

    dim3 ggrid(DFF / 128, NFLAT / 128, E_NUM);   // empty tiles early-exit
    gemm_mma<<<ggrid, 256, SMEM_DYN>>>(0, b1, b2);
    gemm_mma<<<ggrid, 256, SMEM_DYN>>>(1, b1, b2);

    reduce_kernel<<<(B_TOK * (D_DIM / 4) + 255) / 256, 256>>>(out);
    if (out_size >= B_TOK * D_DIM + NFLAT)
        idx_kernel<<<(NFLAT + 255) / 256, 256>>>(out);
}

// round 16
// speedup vs baseline: 2.4434x; 1.0887x over previous
#include <cuda_runtime.h>
#include <cuda_fp16.h>
#include <math.h>
#include <stdint.h>

#define B_TOK 8192
#define D_DIM 1024
#define DFF   1024
#define E_NUM 32
#define NFLAT (B_TOK*2)
#define NPAD  (NFLAT+128)
#define SEGS  64            // NFLAT / 256 == gate grid

// ---------------- scratch (static device globals; no allocation) ----------------
__device__ int   g_top2[NFLAT];
__device__ int   g_offsets[E_NUM+1];
__device__ int   g_disp[NFLAT];
__device__ int   g_segcnt[E_NUM*SEGS];
__device__ int   g_segbase[E_NUM*SEGS];
__device__ __align__(16) __half g_Xf[(size_t)NPAD*D_DIM];
__device__ __align__(16) __half g_Hf[(size_t)NPAD*DFF];
__device__ __align__(16) __half g_wf[2][(size_t)E_NUM*D_DIM*DFF];  // [e][n][k] fp16
__device__ __align__(16) float g_Y[(size_t)NFLAT*D_DIM];

// ---------------- helpers ----------------
__device__ __forceinline__ uint32_t smem_u32(const void* p) {
    uint32_t a;
    asm("{ .reg .u64 t; cvta.to.shared.u64 t, %1; cvt.u32.u64 %0, t; }" : "=r"(a) : "l"(p));
    return a;
}
#define CP16(dst, src) \
    asm volatile("cp.async.cg.shared.global [%0], [%1], 16;" :: "r"(dst), "l"(src) : "memory")
#define CP_COMMIT() asm volatile("cp.async.commit_group;" ::: "memory")
#define CP_WAIT(n)  asm volatile("cp.async.wait_group %0;" :: "n"(n) : "memory")

__device__ __forceinline__ void ldsm4(uint32_t* r, uint32_t addr) {
    asm volatile("ldmatrix.sync.aligned.m8n8.x4.shared.b16 {%0,%1,%2,%3}, [%4];"
        : "=r"(r[0]), "=r"(r[1]), "=r"(r[2]), "=r"(r[3]) : "r"(addr));
}
__device__ __forceinline__ void mma16816h(float* c, const uint32_t* a, const uint32_t* b) {
    asm volatile(
        "mma.sync.aligned.m16n8k16.row.col.f32.f16.f16.f32 "
        "{%0,%1,%2,%3}, {%4,%5,%6,%7}, {%8,%9}, {%0,%1,%2,%3};"
        : "+f"(c[0]), "+f"(c[1]), "+f"(c[2]), "+f"(c[3])
        : "r"(a[0]), "r"(a[1]), "r"(a[2]), "r"(a[3]), "r"(b[0]), "r"(b[1]));
}

// ---------------- gating: logits = X @ Wg + bg, top-2, + fused segment histogram ----------------
// block b covers tokens [128b,128b+128) == flat [256b,256b+256) == segment b exactly.
__global__ void gate_kernel(const float* __restrict__ X,
                            const float* __restrict__ Wg,
                            const float* __restrict__ bg) {
    __shared__ float Xs[32][132];
    __shared__ float Wgs[32][36];
    __shared__ float lg[128][33];
    __shared__ float bgs[32];
    __shared__ int   cnt[E_NUM];

    int tid = threadIdx.x;
    int t0  = blockIdx.x * 128;
    if (tid < 32) { bgs[tid] = bg[tid]; cnt[tid] = 0; }

    int tr = tid & 31;
    int te = tid >> 5;
    float acc[4][4];
#pragma unroll
    for (int i = 0; i < 4; i++)
#pragma unroll
        for (int j = 0; j < 4; j++) acc[i][j] = 0.f;

    for (int k0 = 0; k0 < D_DIM; k0 += 32) {
#pragma unroll
        for (int i = 0; i < 16; i++) {
            int lin = tid + i * 256;
            int r = lin >> 5, c = lin & 31;
            Xs[c][r] = X[(size_t)(t0 + r) * D_DIM + k0 + c];
        }
#pragma unroll
        for (int i = 0; i < 4; i++) {
            int lin = tid + i * 256;
            int r = lin >> 5, c = lin & 31;
            Wgs[r][c] = Wg[(size_t)(k0 + r) * E_NUM + c];
        }
        __syncthreads();
#pragma unroll
        for (int kk = 0; kk < 32; kk++) {
            float4 a4 = *(const float4*)&Xs[kk][tr * 4];
            float4 b4 = *(const float4*)&Wgs[kk][te * 4];
            float av[4] = {a4.x, a4.y, a4.z, a4.w};
            float bv[4] = {b4.x, b4.y, b4.z, b4.w};
#pragma unroll
            for (int i = 0; i < 4; i++)
#pragma unroll
                for (int j = 0; j < 4; j++) acc[i][j] += av[i] * bv[j];
        }
        __syncthreads();
    }
#pragma unroll
    for (int i = 0; i < 4; i++)
#pragma unroll
        for (int j = 0; j < 4; j++)
            lg[tr * 4 + i][te * 4 + j] = acc[i][j] + bgs[te * 4 + j];
    __syncthreads();

    if (tid < 128) {
        int t = t0 + tid;
        float v1 = -INFINITY; int i1 = 0;
        for (int e = 0; e < 32; e++) { float v = lg[tid][e]; if (v > v1) { v1 = v; i1 = e; } }
        float v2 = -INFINITY; int i2 = 0;
        for (int e = 0; e < 32; e++) {
            if (e == i1) continue;
            float v = lg[tid][e]; if (v > v2) { v2 = v; i2 = e; }
        }
        g_top2[t * 2]     = i1;
        g_top2[t * 2 + 1] = i2;
        atomicAdd(&cnt[i1], 1);
        atomicAdd(&cnt[i2], 1);
    }
    __syncthreads();
    if (tid < 32) g_segcnt[tid * SEGS + blockIdx.x] = cnt[tid];
}

// ---------------- stage B: offsets + per-(expert,segment) bases (warp-parallel) ----------------
__global__ void seg_scan_kernel() {
    __shared__ int tot[E_NUM];
    int w = threadIdx.x >> 5, lane = threadIdx.x & 31;
    int c0 = g_segcnt[w * SEGS + lane];
    int c1 = g_segcnt[w * SEGS + 32 + lane];
    int s0 = c0, s1 = c1;
#pragma unroll
    for (int o = 1; o < 32; o <<= 1) {
        int v0 = __shfl_up_sync(0xffffffffu, s0, o);
        int v1 = __shfl_up_sync(0xffffffffu, s1, o);
        if (lane >= o) { s0 += v0; s1 += v1; }
    }
    int t0 = __shfl_sync(0xffffffffu, s0, 31);
    if (lane == 31) tot[w] = s0 + s1;
    __syncthreads();
    if (w == 0) {
        int t = tot[lane];
        int sc = t;
#pragma unroll
        for (int o = 1; o < 32; o <<= 1) {
            int v = __shfl_up_sync(0xffffffffu, sc, o);
            if (lane >= o) sc += v;
        }
        g_offsets[lane] = sc - t;
        if (lane == 31) g_offsets[32] = sc;
    }
    __syncthreads();
    int base = g_offsets[w];
    g_segbase[w * SEGS + lane]      = base + s0 - c0;
    g_segbase[w * SEGS + 32 + lane] = base + t0 + s1 - c1;
}

// ---------------- stage C: stable scatter via warp ballots ----------------
__global__ void scatter_kernel() {
    __shared__ int wcnt[8][E_NUM];
    int tid = threadIdx.x, s = blockIdx.x;
    int w = tid >> 5, lane = tid & 31;
    wcnt[w][lane] = 0;
    __syncthreads();
    int f = s * 256 + tid;
    int e = g_top2[f];
    unsigned peers = __match_any_sync(0xffffffffu, e);
    unsigned lt = peers & ((1u << lane) - 1u);
    int rank = __popc(lt);
    if (lt == 0) wcnt[w][e] = __popc(peers);
    __syncthreads();
    int base = g_segbase[e * SEGS + s] + rank;
#pragma unroll
    for (int w2 = 0; w2 < 8; ++w2) if (w2 < w) base += wcnt[w2][e];
    g_disp[base] = f;
}

// ---------------- weight transpose + fp16 convert: [e][k][n] -> [e][n][k] ----------------
// float4 global loads, smem transpose, 4-half (8B) stores
__global__ void convert_w_kernel(const float* __restrict__ w1, const float* __restrict__ w2) {
    __shared__ float t[64][65];
    int z = blockIdx.z;
    int widx = z >> 5, e = z & 31;
    const float* W = (widx ? w2 : w1) + (size_t)e * D_DIM * DFF;
    __half* O = g_wf[widx] + (size_t)e * D_DIM * DFF;
    int k0 = blockIdx.x * 64, n0 = blockIdx.y * 64;
    int tid = threadIdx.x;
#pragma unroll
    for (int p = 0; p < 4; ++p) {
        int idx = tid + p * 256;          // 0..1023 float4 units
        int k = idx >> 4, c4 = idx & 15;
        float4 v = ((const float4*)&W[(size_t)(k0 + k) * 1024 + n0])[c4];
        t[k][c4 * 4 + 0] = v.x;
        t[k][c4 * 4 + 1] = v.y;
        t[k][c4 * 4 + 2] = v.z;
        t[k][c4 * 4 + 3] = v.w;
    }
    __syncthreads();
    int k4 = (tid & 15) * 4;
    int nb = tid >> 4;
#pragma unroll
    for (int r = 0; r < 4; ++r) {
        int n = nb + r * 16;
        __half2 h01 = __floats2half2_rn(t[k4][n],     t[k4 + 1][n]);
        __half2 h23 = __floats2half2_rn(t[k4 + 2][n], t[k4 + 3][n]);
        uint2 pk;
        pk.x = *(uint32_t*)&h01;
        pk.y = *(uint32_t*)&h23;
        *(uint2*)&O[(size_t)(n0 + n) * 1024 + k0 + k4] = pk;
    }
}

// ---------------- gather dispatched rows + fp16 convert ----------------
__global__ void gather_half_kernel(const float* __restrict__ X) {
    int g = blockIdx.x * 256 + threadIdx.x;   // per float4
    int r = g >> 8, c4 = g & 255;
    int tok = g_disp[r] >> 1;
    float4 v = ((const float4*)X)[(size_t)tok * 256 + c4];
    __half2* H2 = (__half2*)g_Xf;
    size_t o = (size_t)r * 512 + c4 * 2;
    H2[o]     = __floats2half2_rn(v.x, v.y);
    H2[o + 1] = __floats2half2_rn(v.z, v.w);
}

// ---------------- warp-MMA grouped GEMM (fp16, 3-stage cp.async ring + ldmatrix) ----------------
// block tile M=128 x N=128, K chunk=64 (NC=16), 8 warps (2M x 4N), warp tile 64x32.
// smem per buffer: A[128 rows][144B] | B[128 rows][144B]; 3 buffers; ONE barrier per chunk.
#define ROW_S   144
#define BMAT_OFF (128*ROW_S)            // 18432
#define BUF_BYTES (2*128*ROW_S)         // 36864
#define NSTAGE 3
#define SMEM_DYN  (NSTAGE*BUF_BYTES)    // 110592; 2 CTAs/SM = 221184 < 228KB
#define NC 16

__device__ __forceinline__ void fill_cp(uint32_t sbuf, const char* A, const char* B,
                                        int kc, int tid) {
    int kbyte = kc * 128;                // 64 fp16 = 128 B per chunk
#pragma unroll
    for (int i = 0; i < 4; ++i) {
        int idx = tid + i * 256;         // 0..1023
        int row = idx >> 3, sg = (idx & 7) * 16;
        uint32_t dst = sbuf + row * ROW_S + sg;
        size_t src = (size_t)row * 2048 + kbyte + sg;
        CP16(dst,            A + src);
        CP16(dst + BMAT_OFF, B + src);
    }
}

__global__ void __launch_bounds__(256, 2)
gemm_mma(int phase, const float* __restrict__ bias1, const float* __restrict__ bias2) {
    int e   = blockIdx.z;
    int off = g_offsets[e];
    int cnt = g_offsets[e + 1] - off;
    int row0 = blockIdx.y * 128;
    if (row0 >= cnt) return;
    int n0 = blockIdx.x * 128;

    extern __shared__ char dsm[];
    uint32_t sb = smem_u32(dsm);

    int tid = threadIdx.x, wid = tid >> 5, lane = tid & 31;
    int g = lane >> 2, tig = lane & 3;
    int m0w = (wid & 1) * 64;        // warp M base
    int n0w = (wid >> 1) * 32;       // warp N base

    uint32_t aoff = (uint32_t)((m0w + (lane & 15)) * ROW_S + ((lane >> 4) << 4));
    uint32_t boff = (uint32_t)((n0w + ((lane >> 4) << 3) + (lane & 7)) * ROW_S + (((lane >> 3) & 1) << 4));

    const char* A = (const char*)((phase ? g_Hf : g_Xf) + (size_t)(off + row0) * 1024);
    const char* B = (const char*)(g_wf[phase] + ((size_t)e * 1024 + n0) * 1024);
    const float* bias = (phase ? bias2 : bias1) + e * 1024;

    float acc[4][4][4];
#pragma unroll
    for (int mt = 0; mt < 4; mt++)
#pragma unroll
        for (int nt = 0; nt < 4; nt++)
#pragma unroll
            for (int q = 0; q < 4; q++) acc[mt][nt][q] = 0.f;

    fill_cp(sb, A, B, 0, tid);
    CP_COMMIT();
    fill_cp(sb + BUF_BYTES, A, B, 1, tid);
    CP_COMMIT();

    for (int c = 0; c < NC; ++c) {
        // at top of iter c, groups younger than fill(c): only fill(c+1) if it exists
        if (c < NC - 1) { CP_WAIT(1); } else { CP_WAIT(0); }
        __syncthreads();   // single barrier per chunk (3-stage ring makes trailing sync unnecessary)

        uint32_t abuf = sb + (uint32_t)((c % NSTAGE) * BUF_BYTES);
        uint32_t bbuf = abuf + BMAT_OFF;
#pragma unroll
        for (int ks = 0; ks < 4; ++ks) {
            uint32_t kso = ks * 32;
            uint32_t bfr[4][2];
            ldsm4(&bfr[0][0], bbuf + boff + kso);              // nt0, nt1 (n0-15)
            ldsm4(&bfr[2][0], bbuf + boff + kso + 16 * ROW_S); // nt2, nt3 (n16-31)
#pragma unroll
            for (int mt = 0; mt < 4; mt++) {
                uint32_t afr[4];
                ldsm4(afr, abuf + aoff + kso + mt * 16 * ROW_S);
#pragma unroll
                for (int nt = 0; nt < 4; nt++)
                    mma16816h(acc[mt][nt], afr, bfr[nt]);
            }
        }
        if (c + 2 < NC) {
            fill_cp(sb + (uint32_t)(((c + 2) % NSTAGE) * BUF_BYTES), A, B, c + 2, tid);
            CP_COMMIT();
        }
    }

    // epilogue: +bias, (gelu -> fp16 H) or fp32 Y store
#pragma unroll
    for (int mt = 0; mt < 4; mt++) {
#pragma unroll
        for (int rh = 0; rh < 2; rh++) {
            int m = m0w + mt * 16 + g + rh * 8;
            if (row0 + m >= cnt) continue;
            size_t srow = (size_t)(off + row0 + m);
#pragma unroll
            for (int nt = 0; nt < 4; nt++) {
                int n = n0 + n0w + nt * 8 + 2 * tig;
                float v0 = acc[mt][nt][rh * 2]     + bias[n];
                float v1 = acc[mt][nt][rh * 2 + 1] + bias[n + 1];
                if (phase == 0) {
                    v0 = 0.5f * v0 * (1.0f + erff(v0 * 0.7071067811865475f));
                    v1 = 0.5f * v1 * (1.0f + erff(v1 * 0.7071067811865475f));
                    *(__half2*)&g_Hf[srow * 1024 + n] = __floats2half2_rn(v0, v1);
                } else {
                    *(float2*)&g_Y[srow * 1024 + n] = make_float2(v0, v1);
                }
            }
        }
    }
}

// ---------------- pair reduce + idx output (fused) ----------------
__global__ void reduce_kernel(float* __restrict__ out, int do_idx) {
    int i = blockIdx.x * 256 + threadIdx.x;
    const int n4pr = D_DIM / 4;
    int total = B_TOK * n4pr;
    if (i < total) {
        const float4* Y4 = (const float4*)g_Y;
        float4* O4 = (float4*)out;
        int j  = i / n4pr;
        int n4 = i - j * n4pr;
        float4 a = Y4[(size_t)(2 * j) * n4pr + n4];
        float4 b = Y4[(size_t)(2 * j + 1) * n4pr + n4];
        O4[i] = make_float4(a.x + b.x, a.y + b.y, a.z + b.z, a.w + b.w);
    } else if (do_idx && i < total + NFLAT) {
        int j = i - total;
        out[(size_t)B_TOK * D_DIM + j] = (float)g_top2[j];
    }
}

// ---------------- launch ----------------
extern "C" void kernel_launch(void* const* d_in, const int* in_sizes, int n_in,
                              void* d_out, int out_size) {
    const float* X  = (const float*)d_in[0];
    const float* Wg = (const float*)d_in[1];
    const float* bg = (const float*)d_in[2];
    const float* w1 = (const float*)d_in[3];
    const float* b1 = (const float*)d_in[4];
    const float* w2 = (const float*)d_in[5];
    const float* b2 = (const float*)d_in[6];
    float* out = (float*)d_out;

    cudaFuncSetAttribute(gemm_mma, cudaFuncAttributeMaxDynamicSharedMemorySize, SMEM_DYN);

    convert_w_kernel<<<dim3(16, 16, 64), 256>>>(w1, w2);
    gate_kernel<<<B_TOK / 128, 256>>>(X, Wg, bg);          // also emits g_segcnt
    seg_scan_kernel<<<1, 1024>>>();
    scatter_kernel<<<SEGS, 256>>>();
    gather_half_kernel<<<NFLAT, 256>>>(X);

    dim3 ggrid(DFF / 128, NFLAT / 128, E_NUM);   // empty tiles early-exit
    gemm_mma<<<ggrid, 256, SMEM_DYN>>>(0, b1, b2);
    gemm_mma<<<ggrid, 256, SMEM_DYN>>>(1, b1, b2);

    int do_idx = (out_size >= B_TOK * D_DIM + NFLAT) ? 1 : 0;
    int rthreads = B_TOK * (D_DIM / 4) + (do_idx ? NFLAT : 0);
    reduce_kernel<<<(rthreads + 255) / 256, 256>>>(out, do_idx);
}

// round 17
// speedup vs baseline: 2.7898x; 1.1418x over previous
#include <cuda_runtime.h>
#include <cuda_fp16.h>
#include <math.h>
#include <stdint.h>

#define B_TOK 8192
#define D_DIM 1024
#define DFF   1024
#define E_NUM 32
#define NFLAT (B_TOK*2)
#define NPAD  (NFLAT+128)
#define SEGS  64            // NFLAT / 256 == gate grid

// ---------------- scratch (static device globals; no allocation) ----------------
__device__ int   g_top2[NFLAT];
__device__ int   g_offsets[E_NUM+1];
__device__ int   g_disp[NFLAT];
__device__ int   g_segcnt[E_NUM*SEGS];
__device__ int   g_segbase[E_NUM*SEGS];
__device__ int   g_tiles[256];       // packed (expert<<8 | row_tile), built by seg_scan
__device__ int   g_ntiles;           // number of (e,row_tile) entries
__device__ int   g_ctr[2];           // work counters for gemm phase 0/1
__device__ __align__(16) __half g_Xf[(size_t)NPAD*D_DIM];
__device__ __align__(16) __half g_Hf[(size_t)NPAD*DFF];
__device__ __align__(16) __half g_wf[2][(size_t)E_NUM*D_DIM*DFF];  // [e][n][k] fp16
__device__ __align__(16) float g_Y[(size_t)NFLAT*D_DIM];

// ---------------- helpers ----------------
__device__ __forceinline__ uint32_t smem_u32(const void* p) {
    uint32_t a;
    asm("{ .reg .u64 t; cvta.to.shared.u64 t, %1; cvt.u32.u64 %0, t; }" : "=r"(a) : "l"(p));
    return a;
}
#define CP16(dst, src) \
    asm volatile("cp.async.cg.shared.global [%0], [%1], 16;" :: "r"(dst), "l"(src) : "memory")
#define CP_COMMIT() asm volatile("cp.async.commit_group;" ::: "memory")
#define CP_WAIT(n)  asm volatile("cp.async.wait_group %0;" :: "n"(n) : "memory")

__device__ __forceinline__ void ldsm4(uint32_t* r, uint32_t addr) {
    asm volatile("ldmatrix.sync.aligned.m8n8.x4.shared.b16 {%0,%1,%2,%3}, [%4];"
        : "=r"(r[0]), "=r"(r[1]), "=r"(r[2]), "=r"(r[3]) : "r"(addr));
}
__device__ __forceinline__ void mma16816h(float* c, const uint32_t* a, const uint32_t* b) {
    asm volatile(
        "mma.sync.aligned.m16n8k16.row.col.f32.f16.f16.f32 "
        "{%0,%1,%2,%3}, {%4,%5,%6,%7}, {%8,%9}, {%0,%1,%2,%3};"
        : "+f"(c[0]), "+f"(c[1]), "+f"(c[2]), "+f"(c[3])
        : "r"(a[0]), "r"(a[1]), "r"(a[2]), "r"(a[3]), "r"(b[0]), "r"(b[1]));
}

// ---------------- gating: logits = X @ Wg + bg, top-2, + fused segment histogram ----------------
__global__ void gate_kernel(const float* __restrict__ X,
                            const float* __restrict__ Wg,
                            const float* __restrict__ bg) {
    __shared__ float Xs[32][132];
    __shared__ float Wgs[32][36];
    __shared__ float lg[128][33];
    __shared__ float bgs[32];
    __shared__ int   cnt[E_NUM];

    int tid = threadIdx.x;
    int t0  = blockIdx.x * 128;
    if (tid < 32) { bgs[tid] = bg[tid]; cnt[tid] = 0; }

    int tr = tid & 31;
    int te = tid >> 5;
    float acc[4][4];
#pragma unroll
    for (int i = 0; i < 4; i++)
#pragma unroll
        for (int j = 0; j < 4; j++) acc[i][j] = 0.f;

    for (int k0 = 0; k0 < D_DIM; k0 += 32) {
#pragma unroll
        for (int i = 0; i < 16; i++) {
            int lin = tid + i * 256;
            int r = lin >> 5, c = lin & 31;
            Xs[c][r] = X[(size_t)(t0 + r) * D_DIM + k0 + c];
        }
#pragma unroll
        for (int i = 0; i < 4; i++) {
            int lin = tid + i * 256;
            int r = lin >> 5, c = lin & 31;
            Wgs[r][c] = Wg[(size_t)(k0 + r) * E_NUM + c];
        }
        __syncthreads();
#pragma unroll
        for (int kk = 0; kk < 32; kk++) {
            float4 a4 = *(const float4*)&Xs[kk][tr * 4];
            float4 b4 = *(const float4*)&Wgs[kk][te * 4];
            float av[4] = {a4.x, a4.y, a4.z, a4.w};
            float bv[4] = {b4.x, b4.y, b4.z, b4.w};
#pragma unroll
            for (int i = 0; i < 4; i++)
#pragma unroll
                for (int j = 0; j < 4; j++) acc[i][j] += av[i] * bv[j];
        }
        __syncthreads();
    }
#pragma unroll
    for (int i = 0; i < 4; i++)
#pragma unroll
        for (int j = 0; j < 4; j++)
            lg[tr * 4 + i][te * 4 + j] = acc[i][j] + bgs[te * 4 + j];
    __syncthreads();

    if (tid < 128) {
        int t = t0 + tid;
        float v1 = -INFINITY; int i1 = 0;
        for (int e = 0; e < 32; e++) { float v = lg[tid][e]; if (v > v1) { v1 = v; i1 = e; } }
        float v2 = -INFINITY; int i2 = 0;
        for (int e = 0; e < 32; e++) {
            if (e == i1) continue;
            float v = lg[tid][e]; if (v > v2) { v2 = v; i2 = e; }
        }
        g_top2[t * 2]     = i1;
        g_top2[t * 2 + 1] = i2;
        atomicAdd(&cnt[i1], 1);
        atomicAdd(&cnt[i2], 1);
    }
    __syncthreads();
    if (tid < 32) g_segcnt[tid * SEGS + blockIdx.x] = cnt[tid];
}

// ---------------- stage B: offsets + segment bases + tile list + counter reset ----------------
__global__ void seg_scan_kernel() {
    __shared__ int tot[E_NUM];
    int w = threadIdx.x >> 5, lane = threadIdx.x & 31;
    int c0 = g_segcnt[w * SEGS + lane];
    int c1 = g_segcnt[w * SEGS + 32 + lane];
    int s0 = c0, s1 = c1;
#pragma unroll
    for (int o = 1; o < 32; o <<= 1) {
        int v0 = __shfl_up_sync(0xffffffffu, s0, o);
        int v1 = __shfl_up_sync(0xffffffffu, s1, o);
        if (lane >= o) { s0 += v0; s1 += v1; }
    }
    int t0 = __shfl_sync(0xffffffffu, s0, 31);
    if (lane == 31) tot[w] = s0 + s1;
    __syncthreads();
    if (w == 0) {
        int t = tot[lane];
        int sc = t;
#pragma unroll
        for (int o = 1; o < 32; o <<= 1) {
            int v = __shfl_up_sync(0xffffffffu, sc, o);
            if (lane >= o) sc += v;
        }
        g_offsets[lane] = sc - t;
        if (lane == 31) g_offsets[32] = sc;
        // --- build tile list: one entry per (expert, 128-row tile) ---
        int nt = (t + 127) >> 7;
        int ns = nt;
#pragma unroll
        for (int o = 1; o < 32; o <<= 1) {
            int v = __shfl_up_sync(0xffffffffu, ns, o);
            if (lane >= o) ns += v;
        }
        int nbase = ns - nt;
        for (int r = 0; r < nt; ++r) g_tiles[nbase + r] = (lane << 8) | r;
        if (lane == 31) g_ntiles = ns;
        if (lane < 2) g_ctr[lane] = 0;
    }
    __syncthreads();
    int base = g_offsets[w];
    g_segbase[w * SEGS + lane]      = base + s0 - c0;
    g_segbase[w * SEGS + 32 + lane] = base + t0 + s1 - c1;
}

// ---------------- stage C: stable scatter via warp ballots ----------------
__global__ void scatter_kernel() {
    __shared__ int wcnt[8][E_NUM];
    int tid = threadIdx.x, s = blockIdx.x;
    int w = tid >> 5, lane = tid & 31;
    wcnt[w][lane] = 0;
    __syncthreads();
    int f = s * 256 + tid;
    int e = g_top2[f];
    unsigned peers = __match_any_sync(0xffffffffu, e);
    unsigned lt = peers & ((1u << lane) - 1u);
    int rank = __popc(lt);
    if (lt == 0) wcnt[w][e] = __popc(peers);
    __syncthreads();
    int base = g_segbase[e * SEGS + s] + rank;
#pragma unroll
    for (int w2 = 0; w2 < 8; ++w2) if (w2 < w) base += wcnt[w2][e];
    g_disp[base] = f;
}

// ---------------- weight transpose + fp16 convert: [e][k][n] -> [e][n][k] ----------------
__global__ void convert_w_kernel(const float* __restrict__ w1, const float* __restrict__ w2) {
    __shared__ float t[64][65];
    int z = blockIdx.z;
    int widx = z >> 5, e = z & 31;
    const float* W = (widx ? w2 : w1) + (size_t)e * D_DIM * DFF;
    __half* O = g_wf[widx] + (size_t)e * D_DIM * DFF;
    int k0 = blockIdx.x * 64, n0 = blockIdx.y * 64;
    int tid = threadIdx.x;
#pragma unroll
    for (int p = 0; p < 4; ++p) {
        int idx = tid + p * 256;          // 0..1023 float4 units
        int k = idx >> 4, c4 = idx & 15;
        float4 v = ((const float4*)&W[(size_t)(k0 + k) * 1024 + n0])[c4];
        t[k][c4 * 4 + 0] = v.x;
        t[k][c4 * 4 + 1] = v.y;
        t[k][c4 * 4 + 2] = v.z;
        t[k][c4 * 4 + 3] = v.w;
    }
    __syncthreads();
    int k4 = (tid & 15) * 4;
    int nb = tid >> 4;
#pragma unroll
    for (int r = 0; r < 4; ++r) {
        int n = nb + r * 16;
        __half2 h01 = __floats2half2_rn(t[k4][n],     t[k4 + 1][n]);
        __half2 h23 = __floats2half2_rn(t[k4 + 2][n], t[k4 + 3][n]);
        uint2 pk;
        pk.x = *(uint32_t*)&h01;
        pk.y = *(uint32_t*)&h23;
        *(uint2*)&O[(size_t)(n0 + n) * 1024 + k0 + k4] = pk;
    }
}

// ---------------- gather dispatched rows + fp16 convert ----------------
__global__ void gather_half_kernel(const float* __restrict__ X) {
    int g = blockIdx.x * 256 + threadIdx.x;   // per float4
    int r = g >> 8, c4 = g & 255;
    int tok = g_disp[r] >> 1;
    float4 v = ((const float4*)X)[(size_t)tok * 256 + c4];
    __half2* H2 = (__half2*)g_Xf;
    size_t o = (size_t)r * 512 + c4 * 2;
    H2[o]     = __floats2half2_rn(v.x, v.y);
    H2[o + 1] = __floats2half2_rn(v.z, v.w);
}

// ---------------- persistent warp-MMA grouped GEMM (fp16, 3-stage ring + tile stealing) ----------------
// 296 persistent CTAs fetch tiles from g_tiles via atomicAdd. Tile = (e,row0) x 128-col slab.
// smem per buffer: A[128 rows][144B] | B[128 rows][144B]; 3 buffers; one barrier per chunk.
#define ROW_S   144
#define BMAT_OFF (128*ROW_S)            // 18432
#define BUF_BYTES (2*128*ROW_S)         // 36864
#define NSTAGE 3
#define SMEM_DYN  (NSTAGE*BUF_BYTES)    // 110592; 2 CTAs/SM = 221184 < 228KB
#define NC 16
#define GEMM_GRID 296

__device__ __forceinline__ void fill_cp(uint32_t sbuf, const char* A, const char* B,
                                        int kc, int tid) {
    int kbyte = kc * 128;                // 64 fp16 = 128 B per chunk
#pragma unroll
    for (int i = 0; i < 4; ++i) {
        int idx = tid + i * 256;         // 0..1023
        int row = idx >> 3, sg = (idx & 7) * 16;
        uint32_t dst = sbuf + row * ROW_S + sg;
        size_t src = (size_t)row * 2048 + kbyte + sg;
        CP16(dst,            A + src);
        CP16(dst + BMAT_OFF, B + src);
    }
}

__global__ void __launch_bounds__(256, 2)
gemm_mma(int phase, const float* __restrict__ bias1, const float* __restrict__ bias2) {
    extern __shared__ char dsm[];
    uint32_t sb = smem_u32(dsm);
    __shared__ int s_tile;

    int tid = threadIdx.x, wid = tid >> 5, lane = tid & 31;
    int g = lane >> 2, tig = lane & 3;
    int m0w = (wid & 1) * 64;        // warp M base
    int n0w = (wid >> 1) * 32;       // warp N base

    uint32_t aoff = (uint32_t)((m0w + (lane & 15)) * ROW_S + ((lane >> 4) << 4));
    uint32_t boff = (uint32_t)((n0w + ((lane >> 4) << 3) + (lane & 7)) * ROW_S + (((lane >> 3) & 1) << 4));

    const __half* Abase = phase ? g_Hf : g_Xf;
    const __half* Wbase = g_wf[phase];
    const float*  biasb = phase ? bias2 : bias1;
    int ntiles8 = g_ntiles * 8;

    for (;;) {
        if (tid == 0) s_tile = atomicAdd(&g_ctr[phase], 1);
        __syncthreads();                 // publishes s_tile AND guards smem ring reuse
        int t = s_tile;
        if (t >= ntiles8) break;
        int rt = t >> 3, ntile = t & 7;
        int pk = g_tiles[rt];
        int e = pk >> 8;
        int row0 = (pk & 255) * 128;
        int off = g_offsets[e];
        int cnt = g_offsets[e + 1] - off;
        int n0 = ntile * 128;

        const char* A = (const char*)(Abase + (size_t)(off + row0) * 1024);
        const char* B = (const char*)(Wbase + ((size_t)e * 1024 + n0) * 1024);
        const float* bias = biasb + e * 1024;

        float acc[4][4][4];
#pragma unroll
        for (int mt = 0; mt < 4; mt++)
#pragma unroll
            for (int nt = 0; nt < 4; nt++)
#pragma unroll
                for (int q = 0; q < 4; q++) acc[mt][nt][q] = 0.f;

        fill_cp(sb, A, B, 0, tid);
        CP_COMMIT();
        fill_cp(sb + BUF_BYTES, A, B, 1, tid);
        CP_COMMIT();

        for (int c = 0; c < NC; ++c) {
            if (c < NC - 1) { CP_WAIT(1); } else { CP_WAIT(0); }
            __syncthreads();

            uint32_t abuf = sb + (uint32_t)((c % NSTAGE) * BUF_BYTES);
            uint32_t bbuf = abuf + BMAT_OFF;
#pragma unroll
            for (int ks = 0; ks < 4; ++ks) {
                uint32_t kso = ks * 32;
                uint32_t bfr[4][2];
                ldsm4(&bfr[0][0], bbuf + boff + kso);
                ldsm4(&bfr[2][0], bbuf + boff + kso + 16 * ROW_S);
#pragma unroll
                for (int mt = 0; mt < 4; mt++) {
                    uint32_t afr[4];
                    ldsm4(afr, abuf + aoff + kso + mt * 16 * ROW_S);
#pragma unroll
                    for (int nt = 0; nt < 4; nt++)
                        mma16816h(acc[mt][nt], afr, bfr[nt]);
                }
            }
            if (c + 2 < NC) {
                fill_cp(sb + (uint32_t)(((c + 2) % NSTAGE) * BUF_BYTES), A, B, c + 2, tid);
                CP_COMMIT();
            }
        }

        // epilogue: +bias, (gelu -> fp16 H) or fp32 Y store
#pragma unroll
        for (int mt = 0; mt < 4; mt++) {
#pragma unroll
            for (int rh = 0; rh < 2; rh++) {
                int m = m0w + mt * 16 + g + rh * 8;
                if (row0 + m >= cnt) continue;
                size_t srow = (size_t)(off + row0 + m);
#pragma unroll
                for (int nt = 0; nt < 4; nt++) {
                    int n = n0 + n0w + nt * 8 + 2 * tig;
                    float v0 = acc[mt][nt][rh * 2]     + bias[n];
                    float v1 = acc[mt][nt][rh * 2 + 1] + bias[n + 1];
                    if (phase == 0) {
                        v0 = 0.5f * v0 * (1.0f + erff(v0 * 0.7071067811865475f));
                        v1 = 0.5f * v1 * (1.0f + erff(v1 * 0.7071067811865475f));
                        *(__half2*)&g_Hf[srow * 1024 + n] = __floats2half2_rn(v0, v1);
                    } else {
                        *(float2*)&g_Y[srow * 1024 + n] = make_float2(v0, v1);
                    }
                }
            }
        }
    }
}

// ---------------- pair reduce + idx output (fused) ----------------
__global__ void reduce_kernel(float* __restrict__ out, int do_idx) {
    int i = blockIdx.x * 256 + threadIdx.x;
    const int n4pr = D_DIM / 4;
    int total = B_TOK * n4pr;
    if (i < total) {
        const float4* Y4 = (const float4*)g_Y;
        float4* O4 = (float4*)out;
        int j  = i / n4pr;
        int n4 = i - j * n4pr;
        float4 a = Y4[(size_t)(2 * j) * n4pr + n4];
        float4 b = Y4[(size_t)(2 * j + 1) * n4pr + n4];
        O4[i] = make_float4(a.x + b.x, a.y + b.y, a.z + b.z, a.w + b.w);
    } else if (do_idx && i < total + NFLAT) {
        int j = i - total;
        out[(size_t)B_TOK * D_DIM + j] = (float)g_top2[j];
    }
}

// ---------------- launch ----------------
extern "C" void kernel_launch(void* const* d_in, const int* in_sizes, int n_in,
                              void* d_out, int out_size) {
    const float* X  = (const float*)d_in[0];
    const float* Wg = (const float*)d_in[1];
    const float* bg = (const float*)d_in[2];
    const float* w1 = (const float*)d_in[3];
    const float* b1 = (const float*)d_in[4];
    const float* w2 = (const float*)d_in[5];
    const float* b2 = (const float*)d_in[6];
    float* out = (float*)d_out;

    cudaFuncSetAttribute(gemm_mma, cudaFuncAttributeMaxDynamicSharedMemorySize, SMEM_DYN);

    convert_w_kernel<<<dim3(16, 16, 64), 256>>>(w1, w2);
    gate_kernel<<<B_TOK / 128, 256>>>(X, Wg, bg);          // also emits g_segcnt
    seg_scan_kernel<<<1, 1024>>>();                        // offsets + segbase + tile list + ctr reset
    scatter_kernel<<<SEGS, 256>>>();
    gather_half_kernel<<<NFLAT, 256>>>(X);

    gemm_mma<<<GEMM_GRID, 256, SMEM_DYN>>>(0, b1, b2);
    gemm_mma<<<GEMM_GRID, 256, SMEM_DYN>>>(1, b1, b2);

    int do_idx = (out_size >= B_TOK * D_DIM + NFLAT) ? 1 : 0;
    int rthreads = B_TOK * (D_DIM / 4) + (do_idx ? NFLAT : 0);
    reduce_kernel<<<(rthreads + 255) / 256, 256>>>(out, do_idx);
}